// round 6
// baseline (speedup 1.0000x reference)
#include <cuda_runtime.h>

// EMA final-state: y[b,f] = sum_{k=0}^{K-1} 0.5^{k+1} * x[b, T-1-k, f]
// Tail beyond K=16 has relative RMS weight ~2^-16 ~ 1.5e-5, 60x under the
// 1e-3 rel-err gate (K=24 measured 1.4e-7 ~ 2^-24, confirming the model).
//
// Latency-bound kernel -> maximize independent loads in flight:
// 4 threads cooperate per output element (each sums 4 of the 16 terms),
// giving 131072 threads / 512 blocks. Warp lanes cover 32 consecutive f,
// so every load is one coalesced 128B line. Partials combine via smem.

static constexpr int B = 64;
static constexpr int T = 2048;
static constexpr int F = 512;
static constexpr int K = 16;
static constexpr int SPLIT = 4;            // threads per output
static constexpr int KPT = K / SPLIT;      // 4 terms per thread
static constexpr int THREADS = 256;
static constexpr int OUT_PER_BLK = THREADS / SPLIT;   // 64 outputs per block

__global__ void ema_tail_kernel(const float* __restrict__ x, float* __restrict__ out) {
    __shared__ float partial[THREADS];

    int tid = threadIdx.x;
    int lane_out = tid & (OUT_PER_BLK - 1);     // 0..63: which output in block
    int q = tid >> 6;                           // 0..3: which k-chunk

    int oidx = blockIdx.x * OUT_PER_BLK + lane_out;   // 0 .. B*F-1
    int b = oidx >> 9;           // / 512
    int f = oidx & (F - 1);      // % 512

    // this thread covers k = q*KPT .. q*KPT+KPT-1
    int k0 = q * KPT;
    size_t base = ((size_t)b * T + (T - 1 - k0)) * F + f;

    // w for first term of this chunk: 0.5^(k0+1)
    float w = __uint_as_float((127 - (k0 + 1)) << 23);   // exact power of two

    float acc = 0.f;
    #pragma unroll
    for (int k = 0; k < KPT; ++k) {
        acc = fmaf(w, x[base - (size_t)k * F], acc);
        w *= 0.5f;
    }

    partial[tid] = acc;
    __syncthreads();

    if (tid < OUT_PER_BLK) {
        float s = partial[tid]
                + partial[tid + OUT_PER_BLK]
                + partial[tid + 2 * OUT_PER_BLK]
                + partial[tid + 3 * OUT_PER_BLK];
        out[blockIdx.x * OUT_PER_BLK + tid] = s;
    }
}

extern "C" void kernel_launch(void* const* d_in, const int* in_sizes, int n_in,
                              void* d_out, int out_size) {
    const float* x = (const float*)d_in[0];
    float* out = (float*)d_out;

    const int blocks = (B * F) / OUT_PER_BLK;   // 512 blocks
    ema_tail_kernel<<<blocks, THREADS>>>(x, out);
}